// round 3
// baseline (speedup 1.0000x reference)
#include <cuda_runtime.h>

// Problem constants
#define D_MODEL 768
#define SEQ     4096
#define NH      12
#define DKH     64

// ---------------------------------------------------------------------------
// Scratch (no allocations allowed -> device globals)
// ---------------------------------------------------------------------------
__device__ float g_Qp[SEQ * D_MODEL];
__device__ float g_Kp[SEQ * D_MODEL];
__device__ float g_Vp[SEQ * D_MODEL];
__device__ float g_Ctx[SEQ * D_MODEL];

// ---------------------------------------------------------------------------
// GEMM: C[M,N] = A[M,K] @ W[K,N] + bias,  M=4096, N=768, K=768 (all 4 projections)
// 64x64 block tile, 16 K-slice, 256 threads, 4x4 register micro-tile.
// ---------------------------------------------------------------------------
#define GM_BM 64
#define GM_BN 64
#define GM_BK 16
#define GM_K  768
#define GM_N  768

__global__ __launch_bounds__(256, 2)
void gemm_bias(const float* __restrict__ A, const float* __restrict__ W,
               const float* __restrict__ bias, float* __restrict__ C) {
    __shared__ float As[GM_BK][GM_BM + 4];   // [k][m]
    __shared__ float Ws[GM_BK][GM_BN];       // [k][n]

    const int tid = threadIdx.x;
    const int tx = tid & 15;        // n micro
    const int ty = tid >> 4;        // m micro
    const int row0 = blockIdx.y * GM_BM;
    const int col0 = blockIdx.x * GM_BN;

    float acc[4][4];
#pragma unroll
    for (int i = 0; i < 4; i++)
#pragma unroll
        for (int j = 0; j < 4; j++) acc[i][j] = 0.f;

    for (int k0 = 0; k0 < GM_K; k0 += GM_BK) {
        // load A tile 64x16 (transposed into As[k][m])
        {
            const int r = tid >> 2;           // 0..63
            const int c = (tid & 3) * 4;      // 0,4,8,12
            float4 a = *(const float4*)&A[(row0 + r) * GM_K + k0 + c];
            As[c + 0][r] = a.x;
            As[c + 1][r] = a.y;
            As[c + 2][r] = a.z;
            As[c + 3][r] = a.w;
        }
        // load W tile 16x64
        {
            const int r = tid >> 4;           // 0..15
            const int c = (tid & 15) * 4;     // 0..60
            *(float4*)&Ws[r][c] = *(const float4*)&W[(k0 + r) * GM_N + col0 + c];
        }
        __syncthreads();

#pragma unroll
        for (int kk = 0; kk < GM_BK; kk++) {
            float4 av = *(const float4*)&As[kk][ty * 4];
            float4 wv = *(const float4*)&Ws[kk][tx * 4];
            float a[4] = {av.x, av.y, av.z, av.w};
            float w[4] = {wv.x, wv.y, wv.z, wv.w};
#pragma unroll
            for (int i = 0; i < 4; i++)
#pragma unroll
                for (int j = 0; j < 4; j++) acc[i][j] += a[i] * w[j];
        }
        __syncthreads();
    }

#pragma unroll
    for (int i = 0; i < 4; i++) {
        const int r = row0 + ty * 4 + i;
#pragma unroll
        for (int j = 0; j < 4; j++) {
            const int c = col0 + tx * 4 + j;
            C[r * GM_N + c] = acc[i][j] + bias[c];
        }
    }
}

// ---------------------------------------------------------------------------
// Flash attention: one CTA per (head, 64-query tile). 64-wide K/V tiles,
// online softmax in registers, P staged through smem for the PV GEMM.
// Thread layout 16x16; each thread owns 4 rows x 4 cols of S and of O.
// ---------------------------------------------------------------------------
#define FA_BM 64
#define FA_BN 64
#define FA_LD 68                               // row pitch (floats), 16B aligned
#define FA_SMEM (4 * FA_BM * FA_LD * 4)        // Qs,Ks,Vs,Ps

__global__ __launch_bounds__(256, 2)
void flash_attn(const float* __restrict__ Qp, const float* __restrict__ Kp,
                const float* __restrict__ Vp, float* __restrict__ Ctx) {
    extern __shared__ float smem[];
    float* Qs = smem;                    // [64][68]
    float* Ks = Qs + FA_BM * FA_LD;      // [64][68]
    float* Vs = Ks + FA_BM * FA_LD;      // [64][68]
    float* Ps = Vs + FA_BM * FA_LD;      // [64][68]

    const int h  = blockIdx.y;
    const int q0 = blockIdx.x * FA_BM;
    const int tid = threadIdx.x;
    const int tx = tid & 15;
    const int ty = tid >> 4;
    const int hc = h * DKH;
    const float scale = 0.125f;          // 1/sqrt(64)

    // Load Q tile (scaled): rows q0..q0+63, cols hc..hc+63
    for (int i = tid; i < FA_BM * DKH / 4; i += 256) {
        const int r = i >> 4;
        const int c = (i & 15) * 4;
        float4 qv = *(const float4*)&Qp[(q0 + r) * D_MODEL + hc + c];
        qv.x *= scale; qv.y *= scale; qv.z *= scale; qv.w *= scale;
        *(float4*)&Qs[r * FA_LD + c] = qv;
    }

    float m[4], l[4], O[4][4];
#pragma unroll
    for (int i = 0; i < 4; i++) {
        m[i] = -1e30f;
        l[i] = 0.f;
#pragma unroll
        for (int j = 0; j < 4; j++) O[i][j] = 0.f;
    }

    for (int kb = 0; kb < SEQ; kb += FA_BN) {
        __syncthreads();   // previous iter's Ks/Vs/Ps reads complete
        // Load K and V tiles
        for (int i = tid; i < FA_BN * DKH / 4; i += 256) {
            const int r = i >> 4;
            const int c = (i & 15) * 4;
            *(float4*)&Ks[r * FA_LD + c] = *(const float4*)&Kp[(kb + r) * D_MODEL + hc + c];
            *(float4*)&Vs[r * FA_LD + c] = *(const float4*)&Vp[(kb + r) * D_MODEL + hc + c];
        }
        __syncthreads();

        // S = Qs @ Ks^T (scale already folded into Q)
        float S[4][4];
#pragma unroll
        for (int i = 0; i < 4; i++)
#pragma unroll
            for (int j = 0; j < 4; j++) S[i][j] = 0.f;

#pragma unroll
        for (int d = 0; d < DKH; d += 4) {
            float4 qv[4], kv[4];
#pragma unroll
            for (int i = 0; i < 4; i++) qv[i] = *(const float4*)&Qs[(ty * 4 + i) * FA_LD + d];
#pragma unroll
            for (int j = 0; j < 4; j++) kv[j] = *(const float4*)&Ks[(tx * 4 + j) * FA_LD + d];
#pragma unroll
            for (int i = 0; i < 4; i++)
#pragma unroll
                for (int j = 0; j < 4; j++) {
                    S[i][j] += qv[i].x * kv[j].x;
                    S[i][j] += qv[i].y * kv[j].y;
                    S[i][j] += qv[i].z * kv[j].z;
                    S[i][j] += qv[i].w * kv[j].w;
                }
        }

        // Online softmax update (rows owned by 16 lanes sharing ty; width-16 shuffles)
        float corr[4];
#pragma unroll
        for (int i = 0; i < 4; i++) {
            float rmax = fmaxf(fmaxf(S[i][0], S[i][1]), fmaxf(S[i][2], S[i][3]));
#pragma unroll
            for (int off = 8; off > 0; off >>= 1)
                rmax = fmaxf(rmax, __shfl_xor_sync(0xffffffffu, rmax, off, 16));
            const float mnew = fmaxf(m[i], rmax);
            corr[i] = __expf(m[i] - mnew);
            m[i] = mnew;

            float rsum = 0.f;
#pragma unroll
            for (int j = 0; j < 4; j++) {
                const float p = __expf(S[i][j] - mnew);
                Ps[(ty * 4 + i) * FA_LD + tx * 4 + j] = p;
                rsum += p;
            }
#pragma unroll
            for (int off = 8; off > 0; off >>= 1)
                rsum += __shfl_xor_sync(0xffffffffu, rsum, off, 16);
            l[i] = l[i] * corr[i] + rsum;
#pragma unroll
            for (int j = 0; j < 4; j++) O[i][j] *= corr[i];
        }
        __syncthreads();   // Ps visible to all

        // O += Ps @ Vs
#pragma unroll 4
        for (int kk = 0; kk < FA_BN; kk++) {
            float4 vv = *(const float4*)&Vs[kk * FA_LD + tx * 4];
            float pr[4];
#pragma unroll
            for (int i = 0; i < 4; i++) pr[i] = Ps[(ty * 4 + i) * FA_LD + kk];
#pragma unroll
            for (int i = 0; i < 4; i++) {
                O[i][0] += pr[i] * vv.x;
                O[i][1] += pr[i] * vv.y;
                O[i][2] += pr[i] * vv.z;
                O[i][3] += pr[i] * vv.w;
            }
        }
    }

    // Normalize and write out (head-concat layout: Ctx[s][h*64+d])
#pragma unroll
    for (int i = 0; i < 4; i++) {
        const float inv = 1.0f / l[i];
        const int r = q0 + ty * 4 + i;
#pragma unroll
        for (int j = 0; j < 4; j++)
            Ctx[r * D_MODEL + hc + tx * 4 + j] = O[i][j] * inv;
    }
}

// ---------------------------------------------------------------------------
// Launch
// ---------------------------------------------------------------------------
extern "C" void kernel_launch(void* const* d_in, const int* in_sizes, int n_in,
                              void* d_out, int out_size) {
    (void)in_sizes; (void)n_in; (void)out_size;
    const float* q  = (const float*)d_in[0];
    const float* k  = (const float*)d_in[1];
    const float* v  = (const float*)d_in[2];
    const float* Wq = (const float*)d_in[3];
    const float* bq = (const float*)d_in[4];
    const float* Wk = (const float*)d_in[5];
    const float* bk = (const float*)d_in[6];
    const float* Wv = (const float*)d_in[7];
    const float* bv = (const float*)d_in[8];
    const float* Wo = (const float*)d_in[9];
    const float* bo = (const float*)d_in[10];
    float* out = (float*)d_out;

    float *Qp, *Kp, *Vp, *Ctx;
    cudaGetSymbolAddress((void**)&Qp, g_Qp);
    cudaGetSymbolAddress((void**)&Kp, g_Kp);
    cudaGetSymbolAddress((void**)&Vp, g_Vp);
    cudaGetSymbolAddress((void**)&Ctx, g_Ctx);

    const dim3 gg(GM_N / GM_BN, SEQ / GM_BM);   // (12, 64)
    gemm_bias<<<gg, 256>>>(q, Wq, bq, Qp);
    gemm_bias<<<gg, 256>>>(k, Wk, bk, Kp);
    gemm_bias<<<gg, 256>>>(v, Wv, bv, Vp);

    (void)cudaFuncSetAttribute(flash_attn, cudaFuncAttributeMaxDynamicSharedMemorySize, FA_SMEM);
    flash_attn<<<dim3(SEQ / FA_BM, NH), 256, FA_SMEM>>>(Qp, Kp, Vp, Ctx);

    gemm_bias<<<gg, 256>>>(Ctx, Wo, bo, out);
}

// round 5
// speedup vs baseline: 1.0532x; 1.0532x over previous
#include <cuda_runtime.h>
#include <cuda_bf16.h>
#include <cstdint>

// Problem constants
#define D_MODEL 768
#define SEQ     4096
#define NH      12
#define DKH     64

// ---------------------------------------------------------------------------
// Scratch (no allocations allowed -> device globals)
// ---------------------------------------------------------------------------
__device__ __align__(128) float g_Qp[SEQ * D_MODEL];
__device__ __align__(128) float g_Kp[SEQ * D_MODEL];
__device__ __align__(128) float g_Vp[SEQ * D_MODEL];
__device__ __align__(128) float g_Ctx[SEQ * D_MODEL];
__device__ __align__(128) __nv_bfloat16 g_Ah[SEQ * D_MODEL];
__device__ __align__(128) __nv_bfloat16 g_Al[SEQ * D_MODEL];
__device__ __align__(128) __nv_bfloat16 g_Bh[D_MODEL * D_MODEL];
__device__ __align__(128) __nv_bfloat16 g_Bl[D_MODEL * D_MODEL];

// ---------------------------------------------------------------------------
// PTX helpers (all plain-sm_103-legal: HMMA mma.sync, ldmatrix, cp.async)
// ---------------------------------------------------------------------------
__device__ __forceinline__ uint32_t smem_to_u32(const void* p) {
    uint32_t a;
    asm("{ .reg .u64 t; cvta.to.shared.u64 t, %1; cvt.u32.u64 %0, t; }" : "=r"(a) : "l"(p));
    return a;
}
__device__ __forceinline__ void cp16(uint32_t dst, const void* src) {
    asm volatile("cp.async.cg.shared.global [%0], [%1], 16;" :: "r"(dst), "l"(src) : "memory");
}
#define CP_COMMIT() asm volatile("cp.async.commit_group;" ::: "memory")
#define CP_WAIT(n)  asm volatile("cp.async.wait_group %0;" :: "n"(n) : "memory")

__device__ __forceinline__ void ldsm4(uint32_t* r, uint32_t addr) {
    asm volatile("ldmatrix.sync.aligned.m8n8.x4.shared.b16 {%0,%1,%2,%3}, [%4];"
                 : "=r"(r[0]), "=r"(r[1]), "=r"(r[2]), "=r"(r[3]) : "r"(addr));
}
__device__ __forceinline__ void mma16816(float* d, const uint32_t* a, const uint32_t* b) {
    asm volatile("mma.sync.aligned.m16n8k16.row.col.f32.bf16.bf16.f32 "
                 "{%0,%1,%2,%3}, {%4,%5,%6,%7}, {%8,%9}, {%0,%1,%2,%3};"
                 : "+f"(d[0]), "+f"(d[1]), "+f"(d[2]), "+f"(d[3])
                 : "r"(a[0]), "r"(a[1]), "r"(a[2]), "r"(a[3]), "r"(b[0]), "r"(b[1]));
}
__device__ __forceinline__ uint32_t sw128(uint32_t off) { return off ^ ((off >> 3) & 0x70); }

// ---------------------------------------------------------------------------
// Conversion kernels: fp32 -> (bf16 hi, bf16 lo) splits
// ---------------------------------------------------------------------------
__global__ void split_act(const float* __restrict__ A,
                          __nv_bfloat16* __restrict__ hi, __nv_bfloat16* __restrict__ lo) {
    const int i = (blockIdx.x * 256 + threadIdx.x) * 4;
    float4 a = *(const float4*)(A + i);
    float v[4] = {a.x, a.y, a.z, a.w};
#pragma unroll
    for (int j = 0; j < 4; j++) {
        __nv_bfloat16 h = __float2bfloat16(v[j]);
        hi[i + j] = h;
        lo[i + j] = __float2bfloat16(v[j] - __bfloat162float(h));
    }
}

// W[K,N] row-major -> Wt[N,K] K-major, split into hi/lo
__global__ void transpose_split(const float* __restrict__ W,
                                __nv_bfloat16* __restrict__ Th, __nv_bfloat16* __restrict__ Tl) {
    __shared__ float t[32][33];
    const int bx = blockIdx.x * 32;   // n tile
    const int by = blockIdx.y * 32;   // k tile
    const int x = threadIdx.x, y = threadIdx.y;
#pragma unroll
    for (int i = 0; i < 32; i += 8)
        t[y + i][x] = W[(by + y + i) * D_MODEL + bx + x];
    __syncthreads();
#pragma unroll
    for (int i = 0; i < 32; i += 8) {
        const float v = t[x][y + i];
        __nv_bfloat16 h = __float2bfloat16(v);
        const int o = (bx + y + i) * D_MODEL + by + x;
        Th[o] = h;
        Tl[o] = __float2bfloat16(v - __bfloat162float(h));
    }
}

// ---------------------------------------------------------------------------
// HMMA GEMM: C[4096,768] = (Ah+Al)[M,K] @ (Bh+Bl)[N,K]^T + bias
// 3 passes (Ah*Bh + Ah*Bl + Al*Bh) into fp32 register accumulators.
// CTA tile 128x128, BK=64, 8 warps (4M x 2N), warp tile 32x64.
// cp.async double-buffered smem, SW128 swizzle, ldmatrix feeds.
// ---------------------------------------------------------------------------
#define TC_BM 128
#define TC_BN 128
#define TC_BK 64
#define TC_NKCH (D_MODEL / TC_BK)        /* 12 */
#define TC_ITEMS (3 * TC_NKCH)           /* 36 */
#define TC_STAGE 32768                   /* A 16KB + B 16KB per stage */
#define TC_SMEM  (2 * TC_STAGE)

__global__ __launch_bounds__(256)
void gemm_tc(const __nv_bfloat16* __restrict__ Ah, const __nv_bfloat16* __restrict__ Al,
             const __nv_bfloat16* __restrict__ Bh, const __nv_bfloat16* __restrict__ Bl,
             const float* __restrict__ bias, float* __restrict__ C) {
    extern __shared__ char smem[];
    const uint32_t sb = smem_to_u32(smem);
    const int tid  = threadIdx.x;
    const int wid  = tid >> 5;
    const int lane = tid & 31;
    const int row0 = blockIdx.y * TC_BM;
    const int col0 = blockIdx.x * TC_BN;
    const int wm = (wid & 3) * 32;       // warp M offset in tile
    const int wn = (wid >> 2) * 64;      // warp N offset in tile

    float d[2][8][4];
#pragma unroll
    for (int mt = 0; mt < 2; mt++)
#pragma unroll
        for (int nt = 0; nt < 8; nt++)
#pragma unroll
            for (int e = 0; e < 4; e++) d[mt][nt][e] = 0.f;

    // per-thread cp.async source/dest (4 A chunks + 4 B chunks of 16B)
    auto load_item = [&](int item, int stage) {
        const int pass = item / TC_NKCH;
        const int k0 = (item % TC_NKCH) * TC_BK;
        const __nv_bfloat16* Asrc = (pass == 2) ? Al : Ah;
        const __nv_bfloat16* Bsrc = (pass == 1) ? Bl : Bh;
        const uint32_t base = sb + (uint32_t)stage * TC_STAGE;
#pragma unroll
        for (int i = 0; i < 4; i++) {
            const int v = tid + i * 256;
            const int r = v >> 3;          // 0..127
            const int c = v & 7;           // 16B chunk within 128B row
            const uint32_t sw = sw128((uint32_t)(r * 128 + c * 16));
            cp16(base + sw,         Asrc + (size_t)(row0 + r) * D_MODEL + k0 + c * 8);
            cp16(base + 16384 + sw, Bsrc + (size_t)(col0 + r) * D_MODEL + k0 + c * 8);
        }
    };

    load_item(0, 0);
    CP_COMMIT();

    for (int item = 0; item < TC_ITEMS; item++) {
        const int s = item & 1;
        if (item + 1 < TC_ITEMS) {
            load_item(item + 1, s ^ 1);
            CP_COMMIT();
            CP_WAIT(1);
        } else {
            CP_WAIT(0);
        }
        __syncthreads();

        const uint32_t abase = sb + (uint32_t)s * TC_STAGE;
        const uint32_t bbase = abase + 16384;

#pragma unroll
        for (int ks = 0; ks < 4; ks++) {
            uint32_t a[2][4];
#pragma unroll
            for (int mt = 0; mt < 2; mt++) {
                const int r = wm + mt * 16 + (lane & 15);
                const int cb = ks * 32 + ((lane >> 4) << 4);
                ldsm4(a[mt], abase + sw128((uint32_t)(r * 128 + cb)));
            }
            uint32_t b[8][2];
#pragma unroll
            for (int t = 0; t < 4; t++) {
                const int nr = wn + t * 16 + ((lane >> 4) << 3) + (lane & 7);
                const int cb = ks * 32 + ((lane >> 3) & 1) * 16;
                uint32_t bb[4];
                ldsm4(bb, bbase + sw128((uint32_t)(nr * 128 + cb)));
                b[t * 2][0] = bb[0]; b[t * 2][1] = bb[1];
                b[t * 2 + 1][0] = bb[2]; b[t * 2 + 1][1] = bb[3];
            }
#pragma unroll
            for (int mt = 0; mt < 2; mt++)
#pragma unroll
                for (int nt = 0; nt < 8; nt++)
                    mma16816(d[mt][nt], a[mt], b[nt]);
        }
        __syncthreads();
    }

    // Epilogue: fragment -> gmem with bias
#pragma unroll
    for (int mt = 0; mt < 2; mt++) {
        const int rA = row0 + wm + mt * 16 + (lane >> 2);
        const int rB = rA + 8;
#pragma unroll
        for (int nt = 0; nt < 8; nt++) {
            const int c = col0 + wn + nt * 8 + (lane & 3) * 2;
            const float b0 = bias[c], b1 = bias[c + 1];
            float2 o0 = {d[mt][nt][0] + b0, d[mt][nt][1] + b1};
            float2 o1 = {d[mt][nt][2] + b0, d[mt][nt][3] + b1};
            *(float2*)(C + (size_t)rA * D_MODEL + c) = o0;
            *(float2*)(C + (size_t)rB * D_MODEL + c) = o1;
        }
    }
}

// ---------------------------------------------------------------------------
// Flash attention (unchanged SIMT, known-good)
// ---------------------------------------------------------------------------
#define FA_BM 64
#define FA_BN 64
#define FA_LD 68
#define FA_SMEM (4 * FA_BM * FA_LD * 4)

__global__ __launch_bounds__(256, 2)
void flash_attn(const float* __restrict__ Qp, const float* __restrict__ Kp,
                const float* __restrict__ Vp, float* __restrict__ Ctx) {
    extern __shared__ float smemf[];
    float* Qs = smemf;
    float* Ks = Qs + FA_BM * FA_LD;
    float* Vs = Ks + FA_BM * FA_LD;
    float* Ps = Vs + FA_BM * FA_LD;

    const int h  = blockIdx.y;
    const int q0 = blockIdx.x * FA_BM;
    const int tid = threadIdx.x;
    const int tx = tid & 15;
    const int ty = tid >> 4;
    const int hc = h * DKH;
    const float scale = 0.125f;

    for (int i = tid; i < FA_BM * DKH / 4; i += 256) {
        const int r = i >> 4;
        const int c = (i & 15) * 4;
        float4 qv = *(const float4*)&Qp[(q0 + r) * D_MODEL + hc + c];
        qv.x *= scale; qv.y *= scale; qv.z *= scale; qv.w *= scale;
        *(float4*)&Qs[r * FA_LD + c] = qv;
    }

    float m[4], l[4], O[4][4];
#pragma unroll
    for (int i = 0; i < 4; i++) {
        m[i] = -1e30f; l[i] = 0.f;
#pragma unroll
        for (int j = 0; j < 4; j++) O[i][j] = 0.f;
    }

    for (int kb = 0; kb < SEQ; kb += FA_BN) {
        __syncthreads();
        for (int i = tid; i < FA_BN * DKH / 4; i += 256) {
            const int r = i >> 4;
            const int c = (i & 15) * 4;
            *(float4*)&Ks[r * FA_LD + c] = *(const float4*)&Kp[(kb + r) * D_MODEL + hc + c];
            *(float4*)&Vs[r * FA_LD + c] = *(const float4*)&Vp[(kb + r) * D_MODEL + hc + c];
        }
        __syncthreads();

        float S[4][4];
#pragma unroll
        for (int i = 0; i < 4; i++)
#pragma unroll
            for (int j = 0; j < 4; j++) S[i][j] = 0.f;

#pragma unroll
        for (int dd = 0; dd < DKH; dd += 4) {
            float4 qv[4], kv[4];
#pragma unroll
            for (int i = 0; i < 4; i++) qv[i] = *(const float4*)&Qs[(ty * 4 + i) * FA_LD + dd];
#pragma unroll
            for (int j = 0; j < 4; j++) kv[j] = *(const float4*)&Ks[(tx * 4 + j) * FA_LD + dd];
#pragma unroll
            for (int i = 0; i < 4; i++)
#pragma unroll
                for (int j = 0; j < 4; j++) {
                    S[i][j] += qv[i].x * kv[j].x;
                    S[i][j] += qv[i].y * kv[j].y;
                    S[i][j] += qv[i].z * kv[j].z;
                    S[i][j] += qv[i].w * kv[j].w;
                }
        }

        float corr[4];
#pragma unroll
        for (int i = 0; i < 4; i++) {
            float rmax = fmaxf(fmaxf(S[i][0], S[i][1]), fmaxf(S[i][2], S[i][3]));
#pragma unroll
            for (int off = 8; off > 0; off >>= 1)
                rmax = fmaxf(rmax, __shfl_xor_sync(0xffffffffu, rmax, off, 16));
            const float mnew = fmaxf(m[i], rmax);
            corr[i] = __expf(m[i] - mnew);
            m[i] = mnew;

            float rsum = 0.f;
#pragma unroll
            for (int j = 0; j < 4; j++) {
                const float p = __expf(S[i][j] - mnew);
                Ps[(ty * 4 + i) * FA_LD + tx * 4 + j] = p;
                rsum += p;
            }
#pragma unroll
            for (int off = 8; off > 0; off >>= 1)
                rsum += __shfl_xor_sync(0xffffffffu, rsum, off, 16);
            l[i] = l[i] * corr[i] + rsum;
#pragma unroll
            for (int j = 0; j < 4; j++) O[i][j] *= corr[i];
        }
        __syncthreads();

#pragma unroll 4
        for (int kk = 0; kk < FA_BN; kk++) {
            float4 vv = *(const float4*)&Vs[kk * FA_LD + tx * 4];
            float pr[4];
#pragma unroll
            for (int i = 0; i < 4; i++) pr[i] = Ps[(ty * 4 + i) * FA_LD + kk];
#pragma unroll
            for (int i = 0; i < 4; i++) {
                O[i][0] += pr[i] * vv.x;
                O[i][1] += pr[i] * vv.y;
                O[i][2] += pr[i] * vv.z;
                O[i][3] += pr[i] * vv.w;
            }
        }
    }

#pragma unroll
    for (int i = 0; i < 4; i++) {
        const float inv = 1.0f / l[i];
        const int r = q0 + ty * 4 + i;
#pragma unroll
        for (int j = 0; j < 4; j++)
            Ctx[r * D_MODEL + hc + tx * 4 + j] = O[i][j] * inv;
    }
}

// ---------------------------------------------------------------------------
// Launch
// ---------------------------------------------------------------------------
extern "C" void kernel_launch(void* const* d_in, const int* in_sizes, int n_in,
                              void* d_out, int out_size) {
    (void)in_sizes; (void)n_in; (void)out_size;
    const float* q  = (const float*)d_in[0];
    const float* k  = (const float*)d_in[1];
    const float* v  = (const float*)d_in[2];
    const float* Wq = (const float*)d_in[3];
    const float* bq = (const float*)d_in[4];
    const float* Wk = (const float*)d_in[5];
    const float* bk = (const float*)d_in[6];
    const float* Wv = (const float*)d_in[7];
    const float* bv = (const float*)d_in[8];
    const float* Wo = (const float*)d_in[9];
    const float* bo = (const float*)d_in[10];
    float* out = (float*)d_out;

    float *Qp, *Kp, *Vp, *Ctx;
    __nv_bfloat16 *Ah, *Al, *Bh, *Bl;
    cudaGetSymbolAddress((void**)&Qp, g_Qp);
    cudaGetSymbolAddress((void**)&Kp, g_Kp);
    cudaGetSymbolAddress((void**)&Vp, g_Vp);
    cudaGetSymbolAddress((void**)&Ctx, g_Ctx);
    cudaGetSymbolAddress((void**)&Ah, g_Ah);
    cudaGetSymbolAddress((void**)&Al, g_Al);
    cudaGetSymbolAddress((void**)&Bh, g_Bh);
    cudaGetSymbolAddress((void**)&Bl, g_Bl);

    (void)cudaFuncSetAttribute(gemm_tc, cudaFuncAttributeMaxDynamicSharedMemorySize, TC_SMEM);
    (void)cudaFuncSetAttribute(flash_attn, cudaFuncAttributeMaxDynamicSharedMemorySize, FA_SMEM);

    const dim3 tg(D_MODEL / 32, D_MODEL / 32), tb(32, 8);
    const dim3 gg(D_MODEL / TC_BN, SEQ / TC_BM);   // (6, 32)
    const int nsplit = SEQ * D_MODEL / 1024;       // 4 elems/thread, 256 thr/blk

    // Q projection
    transpose_split<<<tg, tb>>>(Wq, Bh, Bl);
    split_act<<<nsplit, 256>>>(q, Ah, Al);
    gemm_tc<<<gg, 256, TC_SMEM>>>(Ah, Al, Bh, Bl, bq, Qp);
    // K projection
    transpose_split<<<tg, tb>>>(Wk, Bh, Bl);
    split_act<<<nsplit, 256>>>(k, Ah, Al);
    gemm_tc<<<gg, 256, TC_SMEM>>>(Ah, Al, Bh, Bl, bk, Kp);
    // V projection
    transpose_split<<<tg, tb>>>(Wv, Bh, Bl);
    split_act<<<nsplit, 256>>>(v, Ah, Al);
    gemm_tc<<<gg, 256, TC_SMEM>>>(Ah, Al, Bh, Bl, bv, Vp);

    // Attention
    flash_attn<<<dim3(SEQ / FA_BM, NH), 256, FA_SMEM>>>(Qp, Kp, Vp, Ctx);

    // Output projection
    transpose_split<<<tg, tb>>>(Wo, Bh, Bl);
    split_act<<<nsplit, 256>>>(Ctx, Ah, Al);
    gemm_tc<<<gg, 256, TC_SMEM>>>(Ah, Al, Bh, Bl, bo, out);
}

// round 10
// speedup vs baseline: 4.3508x; 4.1310x over previous
#include <cuda_runtime.h>
#include <cuda_bf16.h>
#include <cstdint>

// Problem constants
#define D_MODEL 768
#define SEQ     4096
#define NH      12
#define DKH     64

// ---------------------------------------------------------------------------
// Scratch (no allocations allowed -> device globals)
// ---------------------------------------------------------------------------
__device__ __align__(128) __nv_bfloat16 g_Ah[SEQ * D_MODEL];
__device__ __align__(128) __nv_bfloat16 g_Al[SEQ * D_MODEL];
__device__ __align__(128) __nv_bfloat16 g_Bh[D_MODEL * D_MODEL];
__device__ __align__(128) __nv_bfloat16 g_Bl[D_MODEL * D_MODEL];
__device__ __align__(128) __nv_bfloat16 g_Qh[SEQ * D_MODEL];
__device__ __align__(128) __nv_bfloat16 g_Ql[SEQ * D_MODEL];
__device__ __align__(128) __nv_bfloat16 g_Kh[SEQ * D_MODEL];
__device__ __align__(128) __nv_bfloat16 g_Kl[SEQ * D_MODEL];
__device__ __align__(128) __nv_bfloat16 g_Vh[SEQ * D_MODEL];
__device__ __align__(128) __nv_bfloat16 g_Vl[SEQ * D_MODEL];

// ---------------------------------------------------------------------------
// PTX helpers (plain-sm_103-legal: mma.sync, ldmatrix, cp.async)
// ---------------------------------------------------------------------------
__device__ __forceinline__ uint32_t smem_to_u32(const void* p) {
    uint32_t a;
    asm("{ .reg .u64 t; cvta.to.shared.u64 t, %1; cvt.u32.u64 %0, t; }" : "=r"(a) : "l"(p));
    return a;
}
__device__ __forceinline__ void cp16(uint32_t dst, const void* src) {
    asm volatile("cp.async.cg.shared.global [%0], [%1], 16;" :: "r"(dst), "l"(src) : "memory");
}
#define CP_COMMIT() asm volatile("cp.async.commit_group;" ::: "memory")
#define CP_WAIT(n)  asm volatile("cp.async.wait_group %0;" :: "n"(n) : "memory")

__device__ __forceinline__ void ldsm4(uint32_t* r, uint32_t addr) {
    asm volatile("ldmatrix.sync.aligned.m8n8.x4.shared.b16 {%0,%1,%2,%3}, [%4];"
                 : "=r"(r[0]), "=r"(r[1]), "=r"(r[2]), "=r"(r[3]) : "r"(addr));
}
__device__ __forceinline__ void ldsm4t(uint32_t* r, uint32_t addr) {
    asm volatile("ldmatrix.sync.aligned.m8n8.x4.trans.shared.b16 {%0,%1,%2,%3}, [%4];"
                 : "=r"(r[0]), "=r"(r[1]), "=r"(r[2]), "=r"(r[3]) : "r"(addr));
}
__device__ __forceinline__ void mma16816(float* d, const uint32_t* a, const uint32_t* b) {
    asm volatile("mma.sync.aligned.m16n8k16.row.col.f32.bf16.bf16.f32 "
                 "{%0,%1,%2,%3}, {%4,%5,%6,%7}, {%8,%9}, {%0,%1,%2,%3};"
                 : "+f"(d[0]), "+f"(d[1]), "+f"(d[2]), "+f"(d[3])
                 : "r"(a[0]), "r"(a[1]), "r"(a[2]), "r"(a[3]), "r"(b[0]), "r"(b[1]));
}
__device__ __forceinline__ uint32_t sw128(uint32_t off) { return off ^ ((off >> 3) & 0x70); }
__device__ __forceinline__ uint32_t pack2(float a, float b) {
    __nv_bfloat162 t = __floats2bfloat162_rn(a, b);
    return *(uint32_t*)&t;
}

// ---------------------------------------------------------------------------
// Conversion kernels
// ---------------------------------------------------------------------------
__global__ void split_act(const float* __restrict__ A,
                          __nv_bfloat16* __restrict__ hi, __nv_bfloat16* __restrict__ lo) {
    const int i = (blockIdx.x * 256 + threadIdx.x) * 4;
    float4 a = *(const float4*)(A + i);
    float v[4] = {a.x, a.y, a.z, a.w};
#pragma unroll
    for (int j = 0; j < 4; j++) {
        __nv_bfloat16 h = __float2bfloat16(v[j]);
        hi[i + j] = h;
        lo[i + j] = __float2bfloat16(v[j] - __bfloat162float(h));
    }
}

// W[K,N] row-major -> Wt[N,K] K-major, split into hi/lo
__global__ void transpose_split(const float* __restrict__ W,
                                __nv_bfloat16* __restrict__ Th, __nv_bfloat16* __restrict__ Tl) {
    __shared__ float t[32][33];
    const int bx = blockIdx.x * 32;
    const int by = blockIdx.y * 32;
    const int x = threadIdx.x, y = threadIdx.y;
#pragma unroll
    for (int i = 0; i < 32; i += 8)
        t[y + i][x] = W[(by + y + i) * D_MODEL + bx + x];
    __syncthreads();
#pragma unroll
    for (int i = 0; i < 32; i += 8) {
        const float v = t[x][y + i];
        __nv_bfloat16 h = __float2bfloat16(v);
        const int o = (bx + y + i) * D_MODEL + by + x;
        Th[o] = h;
        Tl[o] = __float2bfloat16(v - __bfloat162float(h));
    }
}

// ---------------------------------------------------------------------------
// HMMA GEMM: C = (Ah+Al)[M,K] @ (Bh+Bl)[N,K]^T + bias, optional scale,
// output either fp32 (Cf) or bf16 hi/lo split (Ch/Cl).
// ---------------------------------------------------------------------------
#define TC_BM 128
#define TC_BN 128
#define TC_BK 64
#define TC_NKCH (D_MODEL / TC_BK)
#define TC_ITEMS (3 * TC_NKCH)
#define TC_STAGE 32768
#define TC_SMEM  (2 * TC_STAGE)

__global__ __launch_bounds__(256)
void gemm_tc(const __nv_bfloat16* __restrict__ Ah, const __nv_bfloat16* __restrict__ Al,
             const __nv_bfloat16* __restrict__ Bh, const __nv_bfloat16* __restrict__ Bl,
             const float* __restrict__ bias, float* __restrict__ Cf,
             __nv_bfloat16* __restrict__ Ch, __nv_bfloat16* __restrict__ Cl, float scale) {
    extern __shared__ char smem[];
    const uint32_t sb = smem_to_u32(smem);
    const int tid  = threadIdx.x;
    const int wid  = tid >> 5;
    const int lane = tid & 31;
    const int row0 = blockIdx.y * TC_BM;
    const int col0 = blockIdx.x * TC_BN;
    const int wm = (wid & 3) * 32;
    const int wn = (wid >> 2) * 64;

    float d[2][8][4];
#pragma unroll
    for (int mt = 0; mt < 2; mt++)
#pragma unroll
        for (int nt = 0; nt < 8; nt++)
#pragma unroll
            for (int e = 0; e < 4; e++) d[mt][nt][e] = 0.f;

    auto load_item = [&](int item, int stage) {
        const int pass = item / TC_NKCH;
        const int k0 = (item % TC_NKCH) * TC_BK;
        const __nv_bfloat16* Asrc = (pass == 2) ? Al : Ah;
        const __nv_bfloat16* Bsrc = (pass == 1) ? Bl : Bh;
        const uint32_t base = sb + (uint32_t)stage * TC_STAGE;
#pragma unroll
        for (int i = 0; i < 4; i++) {
            const int v = tid + i * 256;
            const int r = v >> 3;
            const int c = v & 7;
            const uint32_t sw = sw128((uint32_t)(r * 128 + c * 16));
            cp16(base + sw,         Asrc + (size_t)(row0 + r) * D_MODEL + k0 + c * 8);
            cp16(base + 16384 + sw, Bsrc + (size_t)(col0 + r) * D_MODEL + k0 + c * 8);
        }
    };

    load_item(0, 0);
    CP_COMMIT();

    for (int item = 0; item < TC_ITEMS; item++) {
        const int s = item & 1;
        if (item + 1 < TC_ITEMS) {
            load_item(item + 1, s ^ 1);
            CP_COMMIT();
            CP_WAIT(1);
        } else {
            CP_WAIT(0);
        }
        __syncthreads();

        const uint32_t abase = sb + (uint32_t)s * TC_STAGE;
        const uint32_t bbase = abase + 16384;

#pragma unroll
        for (int ks = 0; ks < 4; ks++) {
            uint32_t a[2][4];
#pragma unroll
            for (int mt = 0; mt < 2; mt++) {
                const int r = wm + mt * 16 + (lane & 15);
                const int cb = ks * 32 + ((lane >> 4) << 4);
                ldsm4(a[mt], abase + sw128((uint32_t)(r * 128 + cb)));
            }
#pragma unroll
            for (int t = 0; t < 4; t++) {
                const int nr = wn + t * 16 + ((lane >> 4) << 3) + (lane & 7);
                const int cb = ks * 32 + ((lane >> 3) & 1) * 16;
                uint32_t bb[4];
                ldsm4(bb, bbase + sw128((uint32_t)(nr * 128 + cb)));
#pragma unroll
                for (int mt = 0; mt < 2; mt++) {
                    mma16816(d[mt][t * 2],     a[mt], &bb[0]);
                    mma16816(d[mt][t * 2 + 1], a[mt], &bb[2]);
                }
            }
        }
        __syncthreads();
    }

#pragma unroll
    for (int mt = 0; mt < 2; mt++) {
        const int rA = row0 + wm + mt * 16 + (lane >> 2);
        const int rB = rA + 8;
#pragma unroll
        for (int nt = 0; nt < 8; nt++) {
            const int c = col0 + wn + nt * 8 + (lane & 3) * 2;
            const float b0 = bias[c], b1 = bias[c + 1];
            float v0 = (d[mt][nt][0] + b0) * scale;
            float v1 = (d[mt][nt][1] + b1) * scale;
            float v2 = (d[mt][nt][2] + b0) * scale;
            float v3 = (d[mt][nt][3] + b1) * scale;
            if (Cf) {
                *(float2*)(Cf + (size_t)rA * D_MODEL + c) = make_float2(v0, v1);
                *(float2*)(Cf + (size_t)rB * D_MODEL + c) = make_float2(v2, v3);
            } else {
                __nv_bfloat162 hA = __floats2bfloat162_rn(v0, v1);
                __nv_bfloat162 lA = __floats2bfloat162_rn(v0 - __bfloat162float(hA.x),
                                                          v1 - __bfloat162float(hA.y));
                __nv_bfloat162 hB = __floats2bfloat162_rn(v2, v3);
                __nv_bfloat162 lB = __floats2bfloat162_rn(v2 - __bfloat162float(hB.x),
                                                          v3 - __bfloat162float(hB.y));
                *(__nv_bfloat162*)(Ch + (size_t)rA * D_MODEL + c) = hA;
                *(__nv_bfloat162*)(Cl + (size_t)rA * D_MODEL + c) = lA;
                *(__nv_bfloat162*)(Ch + (size_t)rB * D_MODEL + c) = hB;
                *(__nv_bfloat162*)(Cl + (size_t)rB * D_MODEL + c) = lB;
            }
        }
    }
}

// ---------------------------------------------------------------------------
// HMMA flash attention. CTA = 128 queries x 1 head. 8 warps x m16 rows.
// BN=64 keys/iter, K/V (hi+lo) double-buffered via cp.async.
// S = Qh Kh + Qh Kl + Ql Kh; ctx = Ph Vh + Ph Vl + Pl Vh.
// Writes ctx directly as bf16 hi/lo splits (out-proj A operand).
// ---------------------------------------------------------------------------
#define FB_M 128
#define FB_N 64
#define F_NITER (SEQ / FB_N)          /* 64 */
#define SQH 0
#define SQL 16384
#define SKV 32768                     /* per-stage: Kh 0 | Kl 8K | Vh 16K | Vl 24K */
#define F_STAGE 32768
#define FA2_SMEM (SKV + 2 * F_STAGE)  /* 98304 */

__global__ __launch_bounds__(256)
void flash_tc(const __nv_bfloat16* __restrict__ Qhg, const __nv_bfloat16* __restrict__ Qlg,
              const __nv_bfloat16* __restrict__ Khg, const __nv_bfloat16* __restrict__ Klg,
              const __nv_bfloat16* __restrict__ Vhg, const __nv_bfloat16* __restrict__ Vlg,
              __nv_bfloat16* __restrict__ Ch, __nv_bfloat16* __restrict__ Cl) {
    extern __shared__ char smem[];
    const uint32_t sb = smem_to_u32(smem);
    const int tid  = threadIdx.x;
    const int wid  = tid >> 5;
    const int lane = tid & 31;
    const int q0 = blockIdx.x * FB_M;
    const int hc = blockIdx.y * DKH;
    const int wr = wid * 16;

    // ---- prologue: Q (hi+lo) + KV stage 0 ----
#pragma unroll
    for (int i = 0; i < 4; i++) {
        const int v = tid + i * 256;
        const int r = v >> 3, c = v & 7;
        const uint32_t sw = sw128((uint32_t)(r * 128 + c * 16));
        cp16(sb + SQH + sw, Qhg + (size_t)(q0 + r) * D_MODEL + hc + c * 8);
        cp16(sb + SQL + sw, Qlg + (size_t)(q0 + r) * D_MODEL + hc + c * 8);
    }
    CP_COMMIT();

    const __nv_bfloat16* kvsrc[4] = {Khg, Klg, Vhg, Vlg};
    auto load_kv = [&](int it, int st) {
        const int kb0 = it * FB_N;
        const uint32_t base = sb + SKV + (uint32_t)st * F_STAGE;
#pragma unroll
        for (int i = 0; i < 8; i++) {
            const int mat = i >> 1;                 // compile-time per unrolled i
            const int v = (tid + i * 256) & 511;
            const int r = v >> 3, c = v & 7;
            cp16(base + (uint32_t)mat * 8192u + sw128((uint32_t)(r * 128 + c * 16)),
                 kvsrc[mat] + (size_t)(kb0 + r) * D_MODEL + hc + c * 8);
        }
    };
    load_kv(0, 0);
    CP_COMMIT();
    CP_WAIT(0);
    __syncthreads();

    // ---- resident Q fragments ----
    uint32_t qh[4][4], ql[4][4];
#pragma unroll
    for (int ks = 0; ks < 4; ks++) {
        const int r = wr + (lane & 15);
        const int cb = ks * 32 + ((lane >> 4) << 4);
        const uint32_t off = sw128((uint32_t)(r * 128 + cb));
        ldsm4(qh[ks], sb + SQH + off);
        ldsm4(ql[ks], sb + SQL + off);
    }

    float m0 = -1e30f, m1 = -1e30f, sum0 = 0.f, sum1 = 0.f;
    float O[8][4];
#pragma unroll
    for (int nt = 0; nt < 8; nt++)
#pragma unroll
        for (int e = 0; e < 4; e++) O[nt][e] = 0.f;

#pragma unroll 1
    for (int it = 0; it < F_NITER; it++) {
        const int s = it & 1;
        if (it + 1 < F_NITER) {
            load_kv(it + 1, s ^ 1);
            CP_COMMIT();
            CP_WAIT(1);
        } else {
            CP_WAIT(0);
        }
        __syncthreads();

        const uint32_t kbh = sb + SKV + (uint32_t)s * F_STAGE;
        const uint32_t kbl = kbh + 8192;
        const uint32_t vbh = kbh + 16384;
        const uint32_t vbl = kbh + 24576;

        // ---- S = Q K^T (3-pass split) ----
        float S[8][4];
#pragma unroll
        for (int nt = 0; nt < 8; nt++)
#pragma unroll
            for (int e = 0; e < 4; e++) S[nt][e] = 0.f;

#pragma unroll
        for (int ks = 0; ks < 4; ks++) {
#pragma unroll
            for (int t = 0; t < 4; t++) {
                const int nr = t * 16 + ((lane >> 4) << 3) + (lane & 7);
                const int cb = ks * 32 + ((lane >> 3) & 1) * 16;
                const uint32_t off = sw128((uint32_t)(nr * 128 + cb));
                uint32_t kh4[4], kl4[4];
                ldsm4(kh4, kbh + off);
                ldsm4(kl4, kbl + off);
                mma16816(S[t * 2],     qh[ks], &kh4[0]);
                mma16816(S[t * 2 + 1], qh[ks], &kh4[2]);
                mma16816(S[t * 2],     qh[ks], &kl4[0]);
                mma16816(S[t * 2 + 1], qh[ks], &kl4[2]);
                mma16816(S[t * 2],     ql[ks], &kh4[0]);
                mma16816(S[t * 2 + 1], ql[ks], &kh4[2]);
            }
        }

        // ---- online softmax (rows lane>>2 and +8; quad reduction) ----
        float mx0 = -1e30f, mx1 = -1e30f;
#pragma unroll
        for (int nt = 0; nt < 8; nt++) {
            mx0 = fmaxf(mx0, fmaxf(S[nt][0], S[nt][1]));
            mx1 = fmaxf(mx1, fmaxf(S[nt][2], S[nt][3]));
        }
        mx0 = fmaxf(mx0, __shfl_xor_sync(0xffffffffu, mx0, 1));
        mx0 = fmaxf(mx0, __shfl_xor_sync(0xffffffffu, mx0, 2));
        mx1 = fmaxf(mx1, __shfl_xor_sync(0xffffffffu, mx1, 1));
        mx1 = fmaxf(mx1, __shfl_xor_sync(0xffffffffu, mx1, 2));
        const float mn0 = fmaxf(m0, mx0), mn1 = fmaxf(m1, mx1);
        const float c0 = __expf(m0 - mn0), c1 = __expf(m1 - mn1);
        m0 = mn0; m1 = mn1;

        float rs0 = 0.f, rs1 = 0.f;
#pragma unroll
        for (int nt = 0; nt < 8; nt++) {
            S[nt][0] = __expf(S[nt][0] - mn0);
            S[nt][1] = __expf(S[nt][1] - mn0);
            S[nt][2] = __expf(S[nt][2] - mn1);
            S[nt][3] = __expf(S[nt][3] - mn1);
            rs0 += S[nt][0] + S[nt][1];
            rs1 += S[nt][2] + S[nt][3];
        }
        rs0 += __shfl_xor_sync(0xffffffffu, rs0, 1);
        rs0 += __shfl_xor_sync(0xffffffffu, rs0, 2);
        rs1 += __shfl_xor_sync(0xffffffffu, rs1, 1);
        rs1 += __shfl_xor_sync(0xffffffffu, rs1, 2);
        sum0 = sum0 * c0 + rs0;
        sum1 = sum1 * c1 + rs1;
#pragma unroll
        for (int nt = 0; nt < 8; nt++) {
            O[nt][0] *= c0; O[nt][1] *= c0;
            O[nt][2] *= c1; O[nt][3] *= c1;
        }

        // ---- ctx += P V (3-pass split; P from regs, V via ldmatrix.trans) ----
#pragma unroll
        for (int kt = 0; kt < 4; kt++) {
            uint32_t ph[4], pl[4];
            {
                __nv_bfloat162 h;
                h = __floats2bfloat162_rn(S[2 * kt][0], S[2 * kt][1]);
                ph[0] = *(uint32_t*)&h;
                pl[0] = pack2(S[2 * kt][0] - __bfloat162float(h.x),
                              S[2 * kt][1] - __bfloat162float(h.y));
                h = __floats2bfloat162_rn(S[2 * kt][2], S[2 * kt][3]);
                ph[1] = *(uint32_t*)&h;
                pl[1] = pack2(S[2 * kt][2] - __bfloat162float(h.x),
                              S[2 * kt][3] - __bfloat162float(h.y));
                h = __floats2bfloat162_rn(S[2 * kt + 1][0], S[2 * kt + 1][1]);
                ph[2] = *(uint32_t*)&h;
                pl[2] = pack2(S[2 * kt + 1][0] - __bfloat162float(h.x),
                              S[2 * kt + 1][1] - __bfloat162float(h.y));
                h = __floats2bfloat162_rn(S[2 * kt + 1][2], S[2 * kt + 1][3]);
                ph[3] = *(uint32_t*)&h;
                pl[3] = pack2(S[2 * kt + 1][2] - __bfloat162float(h.x),
                              S[2 * kt + 1][3] - __bfloat162float(h.y));
            }
#pragma unroll
            for (int u = 0; u < 4; u++) {
                const int row = kt * 16 + ((lane >> 3) & 1) * 8 + (lane & 7);
                const int col = u * 32 + (lane >> 4) * 16;
                const uint32_t off = sw128((uint32_t)(row * 128 + col));
                uint32_t vh4[4], vl4[4];
                ldsm4t(vh4, vbh + off);
                ldsm4t(vl4, vbl + off);
                mma16816(O[u * 2],     ph, &vh4[0]);
                mma16816(O[u * 2 + 1], ph, &vh4[2]);
                mma16816(O[u * 2],     ph, &vl4[0]);
                mma16816(O[u * 2 + 1], ph, &vl4[2]);
                mma16816(O[u * 2],     pl, &vh4[0]);
                mma16816(O[u * 2 + 1], pl, &vh4[2]);
            }
        }
        __syncthreads();   // compute done before next iter overwrites stage s^1... (guards s)
    }

    // ---- epilogue: normalize, write ctx bf16 hi/lo ----
    const float inv0 = 1.f / sum0, inv1 = 1.f / sum1;
    const int r0 = q0 + wr + (lane >> 2);
    const int r1 = r0 + 8;
#pragma unroll
    for (int nt = 0; nt < 8; nt++) {
        const int c = hc + nt * 8 + (lane & 3) * 2;
        const float v0 = O[nt][0] * inv0, v1 = O[nt][1] * inv0;
        const float v2 = O[nt][2] * inv1, v3 = O[nt][3] * inv1;
        __nv_bfloat162 hA = __floats2bfloat162_rn(v0, v1);
        __nv_bfloat162 lA = __floats2bfloat162_rn(v0 - __bfloat162float(hA.x),
                                                  v1 - __bfloat162float(hA.y));
        __nv_bfloat162 hB = __floats2bfloat162_rn(v2, v3);
        __nv_bfloat162 lB = __floats2bfloat162_rn(v2 - __bfloat162float(hB.x),
                                                  v3 - __bfloat162float(hB.y));
        *(__nv_bfloat162*)(Ch + (size_t)r0 * D_MODEL + c) = hA;
        *(__nv_bfloat162*)(Cl + (size_t)r0 * D_MODEL + c) = lA;
        *(__nv_bfloat162*)(Ch + (size_t)r1 * D_MODEL + c) = hB;
        *(__nv_bfloat162*)(Cl + (size_t)r1 * D_MODEL + c) = lB;
    }
}

// ---------------------------------------------------------------------------
// Launch
// ---------------------------------------------------------------------------
extern "C" void kernel_launch(void* const* d_in, const int* in_sizes, int n_in,
                              void* d_out, int out_size) {
    (void)in_sizes; (void)n_in; (void)out_size;
    const float* q  = (const float*)d_in[0];
    const float* k  = (const float*)d_in[1];
    const float* v  = (const float*)d_in[2];
    const float* Wq = (const float*)d_in[3];
    const float* bq = (const float*)d_in[4];
    const float* Wk = (const float*)d_in[5];
    const float* bk = (const float*)d_in[6];
    const float* Wv = (const float*)d_in[7];
    const float* bv = (const float*)d_in[8];
    const float* Wo = (const float*)d_in[9];
    const float* bo = (const float*)d_in[10];
    float* out = (float*)d_out;

    __nv_bfloat16 *Ah, *Al, *Bh, *Bl, *Qh, *Ql, *Kh, *Kl, *Vh, *Vl;
    cudaGetSymbolAddress((void**)&Ah, g_Ah);
    cudaGetSymbolAddress((void**)&Al, g_Al);
    cudaGetSymbolAddress((void**)&Bh, g_Bh);
    cudaGetSymbolAddress((void**)&Bl, g_Bl);
    cudaGetSymbolAddress((void**)&Qh, g_Qh);
    cudaGetSymbolAddress((void**)&Ql, g_Ql);
    cudaGetSymbolAddress((void**)&Kh, g_Kh);
    cudaGetSymbolAddress((void**)&Kl, g_Kl);
    cudaGetSymbolAddress((void**)&Vh, g_Vh);
    cudaGetSymbolAddress((void**)&Vl, g_Vl);

    (void)cudaFuncSetAttribute(gemm_tc, cudaFuncAttributeMaxDynamicSharedMemorySize, TC_SMEM);
    (void)cudaFuncSetAttribute(flash_tc, cudaFuncAttributeMaxDynamicSharedMemorySize, FA2_SMEM);

    const dim3 tg(D_MODEL / 32, D_MODEL / 32), tb(32, 8);
    const dim3 gg(D_MODEL / TC_BN, SEQ / TC_BM);   // (6, 32)
    const int nsplit = SEQ * D_MODEL / 1024;

    // Q projection (scale 1/sqrt(dk) folded in), split output
    transpose_split<<<tg, tb>>>(Wq, Bh, Bl);
    split_act<<<nsplit, 256>>>(q, Ah, Al);
    gemm_tc<<<gg, 256, TC_SMEM>>>(Ah, Al, Bh, Bl, bq, nullptr, Qh, Ql, 0.125f);
    // K projection
    transpose_split<<<tg, tb>>>(Wk, Bh, Bl);
    split_act<<<nsplit, 256>>>(k, Ah, Al);
    gemm_tc<<<gg, 256, TC_SMEM>>>(Ah, Al, Bh, Bl, bk, nullptr, Kh, Kl, 1.0f);
    // V projection
    transpose_split<<<tg, tb>>>(Wv, Bh, Bl);
    split_act<<<nsplit, 256>>>(v, Ah, Al);
    gemm_tc<<<gg, 256, TC_SMEM>>>(Ah, Al, Bh, Bl, bv, nullptr, Vh, Vl, 1.0f);

    // Attention: writes ctx splits into Ah/Al (out-proj A operand)
    flash_tc<<<dim3(SEQ / FB_M, NH), 256, FA2_SMEM>>>(Qh, Ql, Kh, Kl, Vh, Vl, Ah, Al);

    // Output projection (fp32 out)
    transpose_split<<<tg, tb>>>(Wo, Bh, Bl);
    gemm_tc<<<gg, 256, TC_SMEM>>>(Ah, Al, Bh, Bl, bo, out, nullptr, nullptr, 1.0f);
}